// round 16
// baseline (speedup 1.0000x reference)
#include <cuda_runtime.h>
#include <math.h>
#include <float.h>

#define NB 148                  // total blocks
#define NBC 128                 // compute blocks = barrier group
#define NSB (NB - NBC)          // 20 free-running helper blocks
#define NT 512
#define WPB (NT/32)
#define NWARPC (NBC*WPB)        // 2048 compute warps
#define HD 1024

// ---- output layout (tuple flattened in order) ----
#define OFF_PA 0        // pred_actions [2,2513]
#define OFF_PV 5026     // pred_verbs   [2,125]
#define OFF_PN 5276     // pred_nouns   [2,352]
#define OFF_PF 5980     // pfeat        [2,1024]
#define OFF_PG 8028     // pgoal        [2,1024]
#define OFF_F2 10076    // f2in         [1,1024]
#define OFF_CA 11100    // cur_action   [1,2513]

// ---- scratch (device globals; no allocation allowed) ----
__device__ unsigned s_maxu[HD];                    // zero-init; re-zeroed each call
__device__ __align__(16) float s_fs[HD];
__device__ __align__(16) float s_gh[5][HD];
__device__ __align__(16) float s_rb[4*HD];
__device__ __align__(16) float s_a[2][10][HD];
__device__ __align__(16) float s_f[2][10][HD];
__device__ float s_dpart[2][10][NBC];              // per-block diff2 partials
__device__ __align__(128) unsigned long long s_cnt;   // monotonic barrier counter

// ---- grid barrier over the NBC compute blocks (R10-proven: atomic + poll) ----
__device__ __forceinline__ void gridbar(unsigned long long base, int k) {
    __syncthreads();
    if (threadIdx.x == 0) {
        asm volatile("red.release.gpu.global.add.u64 [%0], 1;" :: "l"(&s_cnt) : "memory");
        const unsigned long long target = base + (unsigned long long)k * NBC;
        unsigned long long v;
        do {
            asm volatile("ld.acquire.gpu.global.u64 %0, [%1];" : "=l"(v) : "l"(&s_cnt) : "memory");
        } while (v < target);
    }
    __syncthreads();
}

// fast activations (rel err ~1e-6, well under 1e-3 budget)
__device__ __forceinline__ float sigf(float x) {
    return __fdividef(1.0f, 1.0f + __expf(-x));
}
__device__ __forceinline__ float tanhfast(float x) {
    float t = __expf(2.0f * fabsf(x));
    float r = 1.0f - __fdividef(2.0f, t + 1.0f);
    return copysignf(r, x);
}

__device__ __forceinline__ unsigned encf(float f) {
    unsigned u = __float_as_uint(f);
    return (u & 0x80000000u) ? ~u : (u | 0x80000000u);
}

__device__ __forceinline__ float warp_red(float a) {
#pragma unroll
    for (int o = 16; o; o >>= 1) a += __shfl_xor_sync(0xffffffffu, a, o);
    return a;
}

// NOTE: parameter names must not collide with float4 member tokens
#define FMA4(acc, vv, xx) \
    acc = fmaf((vv).x, (xx).x, fmaf((vv).y, (xx).y, fmaf((vv).z, (xx).z, fmaf((vv).w, (xx).w, acc))))

__device__ __forceinline__ float dot1024(const float* __restrict__ w,
                                         const float* __restrict__ x, int lane) {
    float a0 = 0.f, a1 = 0.f;
#pragma unroll
    for (int i = 0; i < 4; ++i) {
        int idx = lane + (i << 6);
        float4 v0 = ((const float4*)w)[idx];
        float4 u0 = ((const float4*)x)[idx];
        float4 v1 = ((const float4*)w)[idx + 32];
        float4 u1 = ((const float4*)x)[idx + 32];
        FMA4(a0, v0, u0);
        FMA4(a1, v1, u1);
    }
    return warp_red(a0 + a1);
}

// ---- one expansion step-phase with register-resident rW_hh (compute blocks only) ----
__device__ __forceinline__ void expand_phase_reg(
    int e, int j, const float4 (&wr)[16],
    const float* __restrict__ Wp,
    float& creg, float rxi, float rxf, float rxg, float rxo,
    float rbase, float rgoal,
    int bid, int wib, int lane,
    float (*sh_part)[6],
    unsigned long long base, int bark) {
    const int slot = wib & 7, half = wib >> 3;
    const int u = bid * 8 + slot;
    const size_t co = (size_t)half * 512;
    const float4* x4 = (const float4*)(s_a[e][j - 1] + co);
    const float4* w4 = (const float4*)(Wp + (size_t)u * 3072 + 1024 + co);
    float a0 = 0.f, a1 = 0.f, a2 = 0.f, a3 = 0.f, a4 = 0.f;
    if (j < 10) {
#pragma unroll
        for (int i = 0; i < 4; ++i) {
            int idx = lane + (i << 5);
            float4 xq = x4[idx];
            float4 v4 = __ldca(w4 + idx);
            FMA4(a0, wr[4 * i + 0], xq);
            FMA4(a1, wr[4 * i + 1], xq);
            FMA4(a2, wr[4 * i + 2], xq);
            FMA4(a3, wr[4 * i + 3], xq);
            FMA4(a4, v4, xq);
        }
#pragma unroll
        for (int o = 16; o; o >>= 1) {
            a0 += __shfl_xor_sync(0xffffffffu, a0, o);
            a1 += __shfl_xor_sync(0xffffffffu, a1, o);
            a2 += __shfl_xor_sync(0xffffffffu, a2, o);
            a3 += __shfl_xor_sync(0xffffffffu, a3, o);
            a4 += __shfl_xor_sync(0xffffffffu, a4, o);
        }
    } else {
#pragma unroll
        for (int i = 0; i < 4; ++i) {
            int idx = lane + (i << 5);
            float4 xq = x4[idx];
            float4 v4 = __ldca(w4 + idx);
            FMA4(a4, v4, xq);
        }
        a4 = warp_red(a4);
    }
    if (lane == 0) {
        sh_part[wib][0] = a0; sh_part[wib][1] = a1; sh_part[wib][2] = a2;
        sh_part[wib][3] = a3; sh_part[wib][4] = a4;
    }
    __syncthreads();
    if (wib == 0 && lane < 8) {
        int uu = bid * 8 + lane;
        float pw = sh_part[lane][4] + sh_part[lane + 8][4];
        float v = fmaxf(pw + rbase, 0.0f);
        s_f[e][j - 1][uu] = v;
        float df = v - rgoal;
        float d2 = df * df;
        d2 += __shfl_down_sync(0xffu, d2, 4, 8);
        d2 += __shfl_down_sync(0xffu, d2, 2, 8);
        d2 += __shfl_down_sync(0xffu, d2, 1, 8);
        if (lane == 0) s_dpart[e][j - 1][bid] = d2;
        if (j < 10) {
            float gi = sh_part[lane][0] + sh_part[lane + 8][0] + rxi;
            float gf = sh_part[lane][1] + sh_part[lane + 8][1] + rxf;
            float gg = sh_part[lane][2] + sh_part[lane + 8][2] + rxg;
            float go = sh_part[lane][3] + sh_part[lane + 8][3] + rxo;
            float cn = sigf(gi) * tanhfast(gg) + sigf(gf) * creg;
            creg = cn;
            s_a[e][j][uu] = sigf(go) * tanhfast(cn);
        }
    }
    gridbar(base, bark);
}

// ---- goal-LSTM layer phase (i,g,o gates; c=0); weights demand-read from DRAM ----
__device__ __forceinline__ void layer_phase(const float* __restrict__ W, int stride4,
                            const float* __restrict__ xin,
                            const float* __restrict__ bi, const float* __restrict__ bh,
                            float* __restrict__ outv,
                            int bid, int wib, int lane, int tid,
                            float* sh_x, float (*sh_part)[6]) {
    if (tid < 256) ((float4*)sh_x)[tid] = ((const float4*)xin)[tid];
    __syncthreads();
    const int slot = wib & 7, half = wib >> 3;
    const int u = bid * 8 + slot;
    const size_t co = (size_t)half * 512;
    const float4* xs4 = (const float4*)(sh_x + co);
    const float4* w0 = (const float4*)(W + (size_t)u * (stride4 * 4) + co);
    float a0 = 0.f, a1 = 0.f, a2 = 0.f;
#pragma unroll
    for (int i = 0; i < 4; ++i) {
        int idx = lane + (i << 5);
        float4 xq = xs4[idx];
        float4 v0 = w0[idx];
        float4 v1 = w0[idx + 2048 * stride4];
        float4 v2 = w0[idx + 3072 * stride4];
        FMA4(a0, v0, xq); FMA4(a1, v1, xq); FMA4(a2, v2, xq);
    }
#pragma unroll
    for (int o = 16; o; o >>= 1) {
        a0 += __shfl_xor_sync(0xffffffffu, a0, o);
        a1 += __shfl_xor_sync(0xffffffffu, a1, o);
        a2 += __shfl_xor_sync(0xffffffffu, a2, o);
    }
    if (lane == 0) { sh_part[wib][0] = a0; sh_part[wib][1] = a1; sh_part[wib][2] = a2; }
    __syncthreads();
    if (wib == 0 && lane < 8) {
        int uu = bid * 8 + lane;
        float gi = sh_part[lane][0] + sh_part[lane + 8][0] + bi[uu] + bh[uu];
        float gg = sh_part[lane][1] + sh_part[lane + 8][1] + bi[uu + 2048] + bh[uu + 2048];
        float go = sh_part[lane][2] + sh_part[lane + 8][2] + bi[uu + 3072] + bh[uu + 3072];
        float cn = sigf(gi) * tanhfast(gg);
        outv[uu] = sigf(go) * tanhfast(cn);
    }
}

__global__ void __launch_bounds__(NT, 1)
va_kernel(const float* __restrict__ tsn,
          const float* __restrict__ W_fe,  const float* __restrict__ b_fe,
          const float* __restrict__ gW_ih0,const float* __restrict__ gW_ihR,
          const float* __restrict__ gb_ih, const float* __restrict__ gb_hh,
          const float* __restrict__ rW_ih, const float* __restrict__ rW_hh,
          const float* __restrict__ rb_ih, const float* __restrict__ rb_hh,
          const float* __restrict__ Wp,    const float* __restrict__ bp,
          const float* __restrict__ We2a,  const float* __restrict__ be2a,
          const float* __restrict__ We2v,  const float* __restrict__ be2v,
          const float* __restrict__ We2n,  const float* __restrict__ be2n,
          float* __restrict__ out) {
    const int tid  = threadIdx.x;
    const int lane = tid & 31;
    const int wib  = tid >> 5;
    const int bid  = blockIdx.x;

    __shared__ float sh_x[3072];
    __shared__ float sh_part[16][6];
    __shared__ float sh_pa[2][HD];
    __shared__ float sh_dv0[10], sh_dv1[10];
    __shared__ float sh_bd0;
    __shared__ int sh_istar, sh_i0, sh_i1;
    __shared__ unsigned long long sh_base;

    if (tid == 0) {
        unsigned long long c0;
        asm volatile("ld.relaxed.gpu.global.u64 %0, [%1];" : "=l"(c0) : "l"(&s_cnt));
        sh_base = c0 - (c0 % (unsigned long long)NBC);
    }
    __syncthreads();
    const unsigned long long base = sh_base;

    // =============== FREE-RUNNING HELPER BLOCKS (no barriers) ===============
    if (bid >= NBC) {
        const int sid = (bid - NBC) * NT + tid;
        const int nst = NSB * NT;
        float acc = 0.f;
        {
            // 1) rW_ih (32 MB) — consumed at P8/E2_pre, streamed during head chain
            const float4* s4 = (const float4*)rW_ih;
            for (size_t i = sid; i < (size_t)4096 * 512; i += (size_t)nst * 4) {
#pragma unroll
                for (int k = 0; k < 4; ++k) {
                    size_t idx = i + (size_t)k * nst;
                    if (idx < (size_t)4096 * 512) {
                        float4 v = __ldcg(s4 + idx);
                        acc += v.x + v.y + v.z + v.w;
                    }
                }
            }
            // 2) prediction heads for cur_action + P_pred
            const float4* p4 = (const float4*)We2a;
            for (size_t i = sid; i < (size_t)2513 * 256; i += (size_t)nst) {
                float4 v = __ldcg(p4 + i);
                acc += v.x + v.y + v.z + v.w;
            }
            const float4* q4 = (const float4*)We2v;
            for (size_t i = sid; i < (size_t)125 * 256; i += (size_t)nst) {
                float4 v = __ldcg(q4 + i);
                acc += v.x + v.y + v.z + v.w;
            }
            const float4* r4 = (const float4*)We2n;
            for (size_t i = sid; i < (size_t)352 * 256; i += (size_t)nst) {
                float4 v = __ldcg(r4 + i);
                acc += v.x + v.y + v.z + v.w;
            }
        }
        asm volatile("" :: "f"(acc));
        // wait until fs is published (after compute barrier #2)
        if (tid == 0) {
            unsigned long long v, t = base + 2ULL * NBC;
            do {
                asm volatile("ld.acquire.gpu.global.u64 %0, [%1];" : "=l"(v) : "l"(&s_cnt) : "memory");
                if (v < t) __nanosleep(128);
            } while (v < t);
        }
        __syncthreads();
        const int swid = (bid - NBC) * WPB + wib;     // 0..319
        for (int r = swid; r < 2513; r += NSB * WPB) {
            float v = dot1024(We2a + (size_t)r * HD, s_fs, lane);
            if (lane == 0) out[OFF_CA + r] = v + be2a[r];
        }
        return;
    }

    // =============== COMPUTE BLOCKS ===============
    const int gwid = bid * WPB + wib;                 // 0..2047
    const int gtid = bid * NT + tid;

    float4 wr[16];                     // register-resident rW_hh half-rows
    float creg = 0.f, rxi = 0.f, rxf = 0.f, rxg = 0.f, rxo = 0.f;
    float rbase = 0.f, rgoal = 0.f;

    // ---------- P0: maxpool + rb + stream Wp & W_fe only (rW_ih moved to helpers) ----------
    {
        const int r0 = bid * 32;
        float m0 = -FLT_MAX, m1 = -FLT_MAX;
        for (int r = r0; r < r0 + 32; ++r) {
            m0 = fmaxf(m0, __ldcg(&tsn[(size_t)r * HD + tid]));
            m1 = fmaxf(m1, __ldcg(&tsn[(size_t)r * HD + 512 + tid]));
        }
        atomicMax(&s_maxu[tid], encf(m0));
        atomicMax(&s_maxu[tid + 512], encf(m1));
        for (int i = gtid; i < 4096; i += NBC * NT) s_rb[i] = rb_ih[i] + rb_hh[i];

        float acc = 0.f;
        const size_t nst = (size_t)NBC * NT;
        auto stream_lin = [&](const float* b, size_t nfl) {
            const float4* p4 = (const float4*)b;
            const size_t n4 = nfl >> 2;
            for (size_t i = gtid; i < n4; i += nst * 4) {
#pragma unroll
                for (int k = 0; k < 4; ++k) {
                    size_t idx = i + (size_t)k * nst;
                    if (idx < n4) {
                        float4 v = __ldcg(p4 + idx);
                        acc += v.x + v.y + v.z + v.w;
                    }
                }
            }
        };
        stream_lin(Wp, (size_t)1024 * 3072);          // 12 MB (22 reuses)
        stream_lin(W_fe, (size_t)HD * HD);            // 4 MB (P2)
        asm volatile("" :: "f"(acc));
    }
    gridbar(base, 1);

    // ---------- P2: fs = W_fe @ maxv + b_fe ----------
    {
        if (tid < 256) {
            uint4 k = ((const uint4*)s_maxu)[tid];
            float4 f;
            f.x = __uint_as_float((k.x & 0x80000000u) ? (k.x & 0x7FFFFFFFu) : ~k.x);
            f.y = __uint_as_float((k.y & 0x80000000u) ? (k.y & 0x7FFFFFFFu) : ~k.y);
            f.z = __uint_as_float((k.z & 0x80000000u) ? (k.z & 0x7FFFFFFFu) : ~k.z);
            f.w = __uint_as_float((k.w & 0x80000000u) ? (k.w & 0x7FFFFFFFu) : ~k.w);
            ((float4*)sh_x)[tid] = f;
        }
        __syncthreads();
        const int slot = wib & 7, half = wib >> 3;
        const int u = bid * 8 + slot;
        const size_t co = (size_t)half * 512;
        const float4* xs4 = (const float4*)(sh_x + co);
        const float4* w0 = (const float4*)(W_fe + (size_t)u * HD + co);
        float a0 = 0.f, a1 = 0.f;
#pragma unroll
        for (int i = 0; i < 2; ++i) {
            int idx = lane + (i << 6);
            float4 x0 = xs4[idx], v0 = w0[idx];
            float4 x1 = xs4[idx + 32], v1 = w0[idx + 32];
            FMA4(a0, v0, x0); FMA4(a1, v1, x1);
        }
        float p = warp_red(a0 + a1);
        if (lane == 0) sh_part[wib][0] = p;
        __syncthreads();
        if (wib == 0 && lane < 8) {
            int uu = bid * 8 + lane;
            s_fs[uu] = sh_part[lane][0] + sh_part[lane + 8][0] + b_fe[uu];
        }
    }
    gridbar(base, 2);

    // ---------- P3: goal layer 0 (weights demand-read) ----------
    if (gtid < HD) s_maxu[gtid] = 0;   // reset for next call
    layer_phase(gW_ih0, 512, s_fs, gb_ih, gb_hh, s_gh[0], bid, wib, lane, tid, sh_x, sh_part);
    gridbar(base, 3);

    // ---------- P4..P7: goal layers 1..4 (weights demand-read) ----------
    for (int l = 1; l <= 4; ++l) {
        layer_phase(gW_ihR + (size_t)(l - 1) * 4096 * 1024, 256, s_gh[l - 1],
                    gb_ih + (size_t)l * 4096, gb_hh + (size_t)l * 4096, s_gh[l],
                    bid, wib, lane, tid, sh_x, sh_part);
        gridbar(base, 3 + l);
    }
    const float* goal = s_gh[4];

    // ---------- P8: E1 xpart(+h0,c0) into REGISTERS; Wp base; wr load ----------
    {
        if (tid < 256) ((float4*)sh_x)[tid] = ((const float4*)s_fs)[tid];
        else           ((float4*)sh_x)[tid] = ((const float4*)goal)[tid - 256];
        __syncthreads();
        const int slot = wib & 7, half = wib >> 3;
        const int u = bid * 8 + slot;
        const size_t co = (size_t)half * 512;
        const float4* xF4 = (const float4*)(sh_x + co);
        const float4* xG4 = (const float4*)(sh_x + 1024 + co);
        const float4* w0 = (const float4*)(rW_ih + (size_t)u * 2048 + 1024 + co);
        const float4* w4 = (const float4*)(Wp + (size_t)u * 3072 + co);
        const float4* w5 = (const float4*)(Wp + (size_t)u * 3072 + 2048 + co);
        const int S4 = 524288;   // 1024 rows * 2048 floats / 4
        float a0 = 0.f, a1 = 0.f, a2 = 0.f, a3 = 0.f, a4 = 0.f, a5 = 0.f;
#pragma unroll
        for (int i = 0; i < 4; ++i) {
            int idx = lane + (i << 5);
            float4 xF = xF4[idx];
            float4 xG = xG4[idx];
            float4 v0 = w0[idx];
            float4 v1 = w0[idx + S4];
            float4 v2 = w0[idx + 2 * S4];
            float4 v3 = w0[idx + 3 * S4];
            float4 v4 = w4[idx];
            float4 v5 = w5[idx];
            FMA4(a0, v0, xF); FMA4(a1, v1, xF); FMA4(a2, v2, xF);
            FMA4(a3, v3, xF); FMA4(a4, v4, xF); FMA4(a5, v5, xG);
        }
#pragma unroll
        for (int o = 16; o; o >>= 1) {
            a0 += __shfl_xor_sync(0xffffffffu, a0, o);
            a1 += __shfl_xor_sync(0xffffffffu, a1, o);
            a2 += __shfl_xor_sync(0xffffffffu, a2, o);
            a3 += __shfl_xor_sync(0xffffffffu, a3, o);
            a4 += __shfl_xor_sync(0xffffffffu, a4, o);
            a5 += __shfl_xor_sync(0xffffffffu, a5, o);
        }
        if (lane == 0) {
            sh_part[wib][0] = a0; sh_part[wib][1] = a1; sh_part[wib][2] = a2;
            sh_part[wib][3] = a3; sh_part[wib][4] = a4; sh_part[wib][5] = a5;
        }
        __syncthreads();
        if (wib == 0 && lane < 8) {
            int uu = bid * 8 + lane;
            rxi = sh_part[lane][0] + sh_part[lane + 8][0] + s_rb[uu];
            rxf = sh_part[lane][1] + sh_part[lane + 8][1] + s_rb[uu + 1024];
            rxg = sh_part[lane][2] + sh_part[lane + 8][2] + s_rb[uu + 2048];
            rxo = sh_part[lane][3] + sh_part[lane + 8][3] + s_rb[uu + 3072];
            rbase = sh_part[lane][4] + sh_part[lane + 8][4]
                  + sh_part[lane][5] + sh_part[lane + 8][5] + bp[uu];
            rgoal = goal[uu];
            float cn = sigf(rxi) * tanhfast(rxg);
            creg = cn;
            s_a[0][0][uu] = sigf(rxo) * tanhfast(cn);
        }
        // load rW_hh half-rows into registers (straight from DRAM; only consumer)
        {
            const float4* wb = (const float4*)(rW_hh + (size_t)u * HD + co);
            const int T4 = 262144;   // 1024*1024/4
#pragma unroll
            for (int i = 0; i < 4; ++i) {
                int idx = lane + (i << 5);
                wr[4 * i + 0] = __ldg(wb + idx);
                wr[4 * i + 1] = __ldg(wb + idx + T4);
                wr[4 * i + 2] = __ldg(wb + idx + 2 * T4);
                wr[4 * i + 3] = __ldg(wb + idx + 3 * T4);
            }
        }
    }
    gridbar(base, 8);

    // ---------- Expansion 1 (j=1..10, barriers 9..18) ----------
    for (int j = 1; j <= 10; ++j)
        expand_phase_reg(0, j, wr, Wp,
                         creg, rxi, rxf, rxg, rxo, rbase, rgoal,
                         bid, wib, lane, sh_part, base, 8 + j);

    // ---------- E2_pre (merged, block-local): dv0+bd0, istar, gates+base+h0 ----------
    {
        if (wib < 10) {
            const float* p = s_dpart[0][wib];
            float acc = p[lane] + p[lane + 32] + p[lane + 64] + p[lane + 96];
            acc = warp_red(acc);
            if (lane == 0) sh_dv0[wib] = acc * (1.0f / 1024.0f);
        } else if (wib == 10) {
            float acc = 0.0f;
            for (int i = lane; i < HD; i += 32) {
                float df = s_fs[i] - goal[i];
                acc = fmaf(df, df, acc);
            }
            acc = warp_red(acc);
            if (lane == 0) sh_bd0 = acc * (1.0f / 1024.0f);
        }
        __syncthreads();
        if (tid == 0) {
            float bd = sh_bd0, best = FLT_MAX; int istar = 0;
#pragma unroll
            for (int jj = 0; jj < 10; ++jj) {
                float dj = sh_dv0[jj];
                float s = bd - dj;
                if (s < best) { best = s; istar = jj; }
                if (dj < bd) bd = dj;
            }
            sh_istar = istar;
        }
        __syncthreads();
        const int istar = sh_istar;
        const float* a2in = s_a[0][istar];
        const float* f2in = s_f[0][istar];
        for (int t = tid; t < 768; t += NT) {
            int which = t >> 8, idx = t & 255;
            const float* src = (which == 0) ? a2in : (which == 1) ? f2in : goal;
            ((float4*)sh_x)[t] = ((const float4*)src)[idx];
        }
        __syncthreads();
        // block-local: this block's 8 rows' E2 gates (2048-wide) + Wp base
        const int slot = wib & 7, half = wib >> 3;
        const int u = bid * 8 + slot;
        const size_t co = (size_t)half * 512;
        const float4* xA4 = (const float4*)(sh_x + co);
        const float4* xF4 = (const float4*)(sh_x + 1024 + co);
        const float4* xG4 = (const float4*)(sh_x + 2048 + co);
        const float4* r0 = (const float4*)(rW_ih + (size_t)u * 2048 + co);
        const float4* r1 = (const float4*)(rW_ih + (size_t)u * 2048 + 1024 + co);
        const float4* w4 = (const float4*)(Wp + (size_t)u * 3072 + co);
        const float4* w5 = (const float4*)(Wp + (size_t)u * 3072 + 2048 + co);
        const int GS4 = 524288;   // 1024 rows * 2048 floats / 4
        float g0 = 0.f, g1 = 0.f, g2 = 0.f, g3 = 0.f, bb = 0.f;
#pragma unroll
        for (int i = 0; i < 4; ++i) {
            int idx = lane + (i << 5);
            float4 xa = xA4[idx];
            float4 xf = xF4[idx];
            float4 xg = xG4[idx];
            float4 va0 = r0[idx];            float4 vf0 = r1[idx];
            float4 va1 = r0[idx + GS4];      float4 vf1 = r1[idx + GS4];
            float4 va2 = r0[idx + 2 * GS4];  float4 vf2 = r1[idx + 2 * GS4];
            float4 va3 = r0[idx + 3 * GS4];  float4 vf3 = r1[idx + 3 * GS4];
            float4 v4 = w4[idx];
            float4 v5 = w5[idx];
            FMA4(g0, va0, xa); FMA4(g0, vf0, xf);
            FMA4(g1, va1, xa); FMA4(g1, vf1, xf);
            FMA4(g2, va2, xa); FMA4(g2, vf2, xf);
            FMA4(g3, va3, xa); FMA4(g3, vf3, xf);
            FMA4(bb, v4, xf);  FMA4(bb, v5, xg);
        }
#pragma unroll
        for (int o = 16; o; o >>= 1) {
            g0 += __shfl_xor_sync(0xffffffffu, g0, o);
            g1 += __shfl_xor_sync(0xffffffffu, g1, o);
            g2 += __shfl_xor_sync(0xffffffffu, g2, o);
            g3 += __shfl_xor_sync(0xffffffffu, g3, o);
            bb += __shfl_xor_sync(0xffffffffu, bb, o);
        }
        if (lane == 0) {
            sh_part[wib][0] = g0; sh_part[wib][1] = g1; sh_part[wib][2] = g2;
            sh_part[wib][3] = g3; sh_part[wib][4] = bb;
        }
        // block 0 emits f2in while its warps are at it
        if (bid == 0) {
            for (int t = tid; t < HD; t += NT) out[OFF_F2 + t] = sh_x[1024 + t];
        }
        __syncthreads();
        if (wib == 0 && lane < 8) {
            int uu = bid * 8 + lane;
            rxi = sh_part[lane][0] + sh_part[lane + 8][0] + s_rb[uu];
            rxf = sh_part[lane][1] + sh_part[lane + 8][1] + s_rb[uu + 1024];
            rxg = sh_part[lane][2] + sh_part[lane + 8][2] + s_rb[uu + 2048];
            rxo = sh_part[lane][3] + sh_part[lane + 8][3] + s_rb[uu + 3072];
            rbase = sh_part[lane][4] + sh_part[lane + 8][4] + bp[uu];
            float cn = sigf(rxi) * tanhfast(rxg);
            creg = cn;
            s_a[1][0][uu] = sigf(rxo) * tanhfast(cn);
        }
    }
    gridbar(base, 19);

    // ---------- Expansion 2 (j=1..10, barriers 20..29) ----------
    for (int j = 1; j <= 10; ++j)
        expand_phase_reg(1, j, wr, Wp,
                         creg, rxi, rxf, rxg, rxo, rbase, rgoal,
                         bid, wib, lane, sh_part, base, 19 + j);

    // ---------- Final: d[1][*] reduce, scan + outputs (no more barriers) ----------
    {
        if (wib < 10) {
            const float* p = s_dpart[1][wib];
            float acc = p[lane] + p[lane + 32] + p[lane + 64] + p[lane + 96];
            acc = warp_red(acc);
            if (lane == 0) sh_dv1[wib] = acc * (1.0f / 1024.0f);
        }
        __syncthreads();
        if (tid == 0) {
            float bd = sh_bd0, best = FLT_MAX; int istar = 0;
            float s1[10], s2[10];
#pragma unroll
            for (int jj = 0; jj < 10; ++jj) {
                float dj = sh_dv0[jj];
                s1[jj] = bd - dj;
                if (s1[jj] < best) { best = s1[jj]; istar = jj; }
                if (dj < bd) bd = dj;
            }
#pragma unroll
            for (int jj = 0; jj < 10; ++jj) {
                float dj = sh_dv1[jj];
                s2[jj] = bd - dj;
                if (dj < bd) bd = dj;
            }
            float b0 = FLT_MAX, b1 = FLT_MAX; int i0 = 0, i1 = 0;
#pragma unroll
            for (int k = 0; k < 20; ++k) {
                float v = (k < 10) ? ((k == istar) ? FLT_MAX : s1[k]) : s2[k - 10];
                if (v < b0) { b1 = b0; i1 = i0; b0 = v; i0 = k; }
                else if (v < b1) { b1 = v; i1 = k; }
            }
            sh_istar = istar; sh_i0 = i0; sh_i1 = i1;
        }
        __syncthreads();
        const int istar = sh_istar;
        const float* a2in = s_a[0][istar];
        const float* f2in = s_f[0][istar];

        for (int t = tid; t < 2048; t += NT) {
            int which = t >> 10, col = t & 1023;
            int idx = which ? sh_i1 : sh_i0;
            float pa;
            if (idx < 10) pa = s_a[0][idx][col] * 0.5f;
            else          pa = (a2in[col] + s_a[1][idx - 10][col]) * (1.0f / 3.0f);
            sh_pa[which][col] = pa;
        }
        if (bid == 0) {
            for (int t = tid; t < 2048; t += NT) {
                int which = t >> 10, col = t & 1023;
                int idx = which ? sh_i1 : sh_i0;
                float pfv;
                if (idx < 10) pfv = (s_fs[col] + s_f[0][idx][col]) * 0.5f;
                else          pfv = (s_fs[col] + f2in[col] + s_f[1][idx - 10][col]) * (1.0f / 3.0f);
                out[OFF_PF + which * HD + col] = pfv;
                out[OFF_PG + which * HD + col] = goal[col];
            }
        }
        __syncthreads();

        // paired prediction dots across compute warps
        for (int rr = gwid; rr < 2990; rr += NWARPC) {
            const float* W; const float* bias; int off, rows, r;
            if (rr < 2513)      { W = We2a; bias = be2a; off = OFF_PA; rows = 2513; r = rr; }
            else if (rr < 2638) { W = We2v; bias = be2v; off = OFF_PV; rows = 125;  r = rr - 2513; }
            else                { W = We2n; bias = be2n; off = OFF_PN; rows = 352;  r = rr - 2638; }
            const float4* row4 = (const float4*)(W + (size_t)r * HD);
            float a0 = 0.f, a1 = 0.f;
#pragma unroll
            for (int i = 0; i < 8; ++i) {
                int idx = lane + (i << 5);
                float4 wv = row4[idx];
                float4 ua = ((const float4*)sh_pa[0])[idx];
                float4 ub = ((const float4*)sh_pa[1])[idx];
                FMA4(a0, wv, ua);
                FMA4(a1, wv, ub);
            }
#pragma unroll
            for (int o = 16; o; o >>= 1) {
                a0 += __shfl_xor_sync(0xffffffffu, a0, o);
                a1 += __shfl_xor_sync(0xffffffffu, a1, o);
            }
            if (lane == 0) {
                out[off + r] = a0 + bias[r];
                out[off + rows + r] = a1 + bias[r];
            }
        }
    }
}

extern "C" void kernel_launch(void* const* d_in, const int* in_sizes, int n_in,
                              void* d_out, int out_size) {
    const float* tsn    = (const float*)d_in[0];
    const float* W_fe   = (const float*)d_in[1];
    const float* b_fe   = (const float*)d_in[2];
    const float* gW_ih0 = (const float*)d_in[3];
    const float* gW_ihR = (const float*)d_in[4];
    // d_in[5] = gW_hh : multiplied by zero hidden state everywhere -> unused
    const float* gb_ih  = (const float*)d_in[6];
    const float* gb_hh  = (const float*)d_in[7];
    const float* rW_ih  = (const float*)d_in[8];
    const float* rW_hh  = (const float*)d_in[9];
    const float* rb_ih  = (const float*)d_in[10];
    const float* rb_hh  = (const float*)d_in[11];
    const float* Wp     = (const float*)d_in[12];
    const float* bp     = (const float*)d_in[13];
    const float* We2a   = (const float*)d_in[14];
    const float* be2a   = (const float*)d_in[15];
    const float* We2v   = (const float*)d_in[16];
    const float* be2v   = (const float*)d_in[17];
    const float* We2n   = (const float*)d_in[18];
    const float* be2n   = (const float*)d_in[19];

    va_kernel<<<NB, NT>>>(tsn, W_fe, b_fe, gW_ih0, gW_ihR, gb_ih, gb_hh,
                          rW_ih, rW_hh, rb_ih, rb_hh, Wp, bp,
                          We2a, be2a, We2v, be2v, We2n, be2n,
                          (float*)d_out);
}

// round 17
// speedup vs baseline: 1.0502x; 1.0502x over previous
#include <cuda_runtime.h>
#include <math.h>
#include <float.h>

#define NB 148                  // total blocks
#define NBC 128                 // compute blocks = barrier group
#define NSB (NB - NBC)          // 20 free-running helper blocks
#define NT 512
#define WPB (NT/32)
#define NWARPC (NBC*WPB)        // 2048 compute warps
#define HD 1024

// ---- output layout (tuple flattened in order) ----
#define OFF_PA 0        // pred_actions [2,2513]
#define OFF_PV 5026     // pred_verbs   [2,125]
#define OFF_PN 5276     // pred_nouns   [2,352]
#define OFF_PF 5980     // pfeat        [2,1024]
#define OFF_PG 8028     // pgoal        [2,1024]
#define OFF_F2 10076    // f2in         [1,1024]
#define OFF_CA 11100    // cur_action   [1,2513]

// ---- scratch (device globals; no allocation allowed) ----
__device__ unsigned s_maxu[HD];                    // zero-init; re-zeroed each call
__device__ __align__(16) float s_fs[HD];
__device__ __align__(16) float s_gh[5][HD];
__device__ __align__(16) float s_rb[4*HD];
__device__ __align__(16) float s_a[2][10][HD];
__device__ __align__(16) float s_f[2][10][HD];
__device__ float s_dpart[2][10][NBC];              // per-block diff2 partials
__device__ __align__(128) unsigned long long s_cnt;   // monotonic barrier counter

// ---- grid barrier over the NBC compute blocks (R10-proven: atomic + poll) ----
__device__ __forceinline__ void gridbar(unsigned long long base, int k) {
    __syncthreads();
    if (threadIdx.x == 0) {
        asm volatile("red.release.gpu.global.add.u64 [%0], 1;" :: "l"(&s_cnt) : "memory");
        const unsigned long long target = base + (unsigned long long)k * NBC;
        unsigned long long v;
        do {
            asm volatile("ld.acquire.gpu.global.u64 %0, [%1];" : "=l"(v) : "l"(&s_cnt) : "memory");
        } while (v < target);
    }
    __syncthreads();
}

// fast activations (rel err ~1e-6, well under 1e-3 budget)
__device__ __forceinline__ float sigf(float x) {
    return __fdividef(1.0f, 1.0f + __expf(-x));
}
__device__ __forceinline__ float tanhfast(float x) {
    float t = __expf(2.0f * fabsf(x));
    float r = 1.0f - __fdividef(2.0f, t + 1.0f);
    return copysignf(r, x);
}

__device__ __forceinline__ unsigned encf(float f) {
    unsigned u = __float_as_uint(f);
    return (u & 0x80000000u) ? ~u : (u | 0x80000000u);
}

__device__ __forceinline__ float warp_red(float a) {
#pragma unroll
    for (int o = 16; o; o >>= 1) a += __shfl_xor_sync(0xffffffffu, a, o);
    return a;
}

// NOTE: parameter names must not collide with float4 member tokens
#define FMA4(acc, vv, xx) \
    acc = fmaf((vv).x, (xx).x, fmaf((vv).y, (xx).y, fmaf((vv).z, (xx).z, fmaf((vv).w, (xx).w, acc))))

__device__ __forceinline__ float dot1024(const float* __restrict__ w,
                                         const float* __restrict__ x, int lane) {
    float a0 = 0.f, a1 = 0.f;
#pragma unroll
    for (int i = 0; i < 4; ++i) {
        int idx = lane + (i << 6);
        float4 v0 = ((const float4*)w)[idx];
        float4 u0 = ((const float4*)x)[idx];
        float4 v1 = ((const float4*)w)[idx + 32];
        float4 u1 = ((const float4*)x)[idx + 32];
        FMA4(a0, v0, u0);
        FMA4(a1, v1, u1);
    }
    return warp_red(a0 + a1);
}

// ---- one expansion step-phase with register-resident rW_hh (compute blocks only) ----
__device__ __forceinline__ void expand_phase_reg(
    int e, int j, const float4 (&wr)[16],
    const float* __restrict__ Wp,
    float& creg, float rxi, float rxf, float rxg, float rxo,
    float rbase, float rgoal,
    int bid, int wib, int lane,
    float (*sh_part)[6],
    unsigned long long base, int bark) {
    const int slot = wib & 7, half = wib >> 3;
    const int u = bid * 8 + slot;
    const size_t co = (size_t)half * 512;
    const float4* x4 = (const float4*)(s_a[e][j - 1] + co);
    const float4* w4 = (const float4*)(Wp + (size_t)u * 3072 + 1024 + co);
    float a0 = 0.f, a1 = 0.f, a2 = 0.f, a3 = 0.f, a4 = 0.f;
    if (j < 10) {
#pragma unroll
        for (int i = 0; i < 4; ++i) {
            int idx = lane + (i << 5);
            float4 xq = x4[idx];
            float4 v4 = __ldca(w4 + idx);
            FMA4(a0, wr[4 * i + 0], xq);
            FMA4(a1, wr[4 * i + 1], xq);
            FMA4(a2, wr[4 * i + 2], xq);
            FMA4(a3, wr[4 * i + 3], xq);
            FMA4(a4, v4, xq);
        }
#pragma unroll
        for (int o = 16; o; o >>= 1) {
            a0 += __shfl_xor_sync(0xffffffffu, a0, o);
            a1 += __shfl_xor_sync(0xffffffffu, a1, o);
            a2 += __shfl_xor_sync(0xffffffffu, a2, o);
            a3 += __shfl_xor_sync(0xffffffffu, a3, o);
            a4 += __shfl_xor_sync(0xffffffffu, a4, o);
        }
    } else {
#pragma unroll
        for (int i = 0; i < 4; ++i) {
            int idx = lane + (i << 5);
            float4 xq = x4[idx];
            float4 v4 = __ldca(w4 + idx);
            FMA4(a4, v4, xq);
        }
        a4 = warp_red(a4);
    }
    if (lane == 0) {
        sh_part[wib][0] = a0; sh_part[wib][1] = a1; sh_part[wib][2] = a2;
        sh_part[wib][3] = a3; sh_part[wib][4] = a4;
    }
    __syncthreads();
    if (wib == 0 && lane < 8) {
        int uu = bid * 8 + lane;
        float pw = sh_part[lane][4] + sh_part[lane + 8][4];
        float v = fmaxf(pw + rbase, 0.0f);
        s_f[e][j - 1][uu] = v;
        float df = v - rgoal;
        float d2 = df * df;
        d2 += __shfl_down_sync(0xffu, d2, 4, 8);
        d2 += __shfl_down_sync(0xffu, d2, 2, 8);
        d2 += __shfl_down_sync(0xffu, d2, 1, 8);
        if (lane == 0) s_dpart[e][j - 1][bid] = d2;
        if (j < 10) {
            float gi = sh_part[lane][0] + sh_part[lane + 8][0] + rxi;
            float gf = sh_part[lane][1] + sh_part[lane + 8][1] + rxf;
            float gg = sh_part[lane][2] + sh_part[lane + 8][2] + rxg;
            float go = sh_part[lane][3] + sh_part[lane + 8][3] + rxo;
            float cn = sigf(gi) * tanhfast(gg) + sigf(gf) * creg;
            creg = cn;
            s_a[e][j][uu] = sigf(go) * tanhfast(cn);
        }
    }
    gridbar(base, bark);
}

__global__ void __launch_bounds__(NT, 1)
va_kernel(const float* __restrict__ tsn,
          const float* __restrict__ W_fe,  const float* __restrict__ b_fe,
          const float* __restrict__ gW_ih0,const float* __restrict__ gW_ihR,
          const float* __restrict__ gb_ih, const float* __restrict__ gb_hh,
          const float* __restrict__ rW_ih, const float* __restrict__ rW_hh,
          const float* __restrict__ rb_ih, const float* __restrict__ rb_hh,
          const float* __restrict__ Wp,    const float* __restrict__ bp,
          const float* __restrict__ We2a,  const float* __restrict__ be2a,
          const float* __restrict__ We2v,  const float* __restrict__ be2v,
          const float* __restrict__ We2n,  const float* __restrict__ be2n,
          float* __restrict__ out) {
    const int tid  = threadIdx.x;
    const int lane = tid & 31;
    const int wib  = tid >> 5;
    const int bid  = blockIdx.x;

    __shared__ float sh_x[3072];
    __shared__ float sh_part[16][6];
    __shared__ float sh_pa[2][HD];
    __shared__ float sh_dv0[10], sh_dv1[10];
    __shared__ float sh_bd0;
    __shared__ int sh_istar, sh_i0, sh_i1;
    __shared__ unsigned long long sh_base;

    if (tid == 0) {
        unsigned long long c0;
        asm volatile("ld.relaxed.gpu.global.u64 %0, [%1];" : "=l"(c0) : "l"(&s_cnt));
        sh_base = c0 - (c0 % (unsigned long long)NBC);
    }
    __syncthreads();
    const unsigned long long base = sh_base;

    // =============== FREE-RUNNING HELPER BLOCKS (no barriers) ===============
    if (bid >= NBC) {
        const int sid = (bid - NBC) * NT + tid;
        const int nst = NSB * NT;
        float acc = 0.f;
        {
            const float4* p4 = (const float4*)We2a;
            for (size_t i = sid; i < (size_t)2513 * 256; i += (size_t)nst) {
                float4 v = __ldcg(p4 + i);
                acc += v.x + v.y + v.z + v.w;
            }
            const float4* q4 = (const float4*)We2v;
            for (size_t i = sid; i < (size_t)125 * 256; i += (size_t)nst) {
                float4 v = __ldcg(q4 + i);
                acc += v.x + v.y + v.z + v.w;
            }
            const float4* r4 = (const float4*)We2n;
            for (size_t i = sid; i < (size_t)352 * 256; i += (size_t)nst) {
                float4 v = __ldcg(r4 + i);
                acc += v.x + v.y + v.z + v.w;
            }
        }
        asm volatile("" :: "f"(acc));
        // wait until fs is published (after compute barrier #2)
        if (tid == 0) {
            unsigned long long v, t = base + 2ULL * NBC;
            do {
                asm volatile("ld.acquire.gpu.global.u64 %0, [%1];" : "=l"(v) : "l"(&s_cnt) : "memory");
                if (v < t) __nanosleep(128);
            } while (v < t);
        }
        __syncthreads();
        const int swid = (bid - NBC) * WPB + wib;     // 0..319
        for (int r = swid; r < 2513; r += NSB * WPB) {
            float v = dot1024(We2a + (size_t)r * HD, s_fs, lane);
            if (lane == 0) out[OFF_CA + r] = v + be2a[r];
        }
        return;
    }

    // =============== COMPUTE BLOCKS ===============
    const int gwid = bid * WPB + wib;                 // 0..2047
    const int gtid = bid * NT + tid;
    const int slot = wib & 7, half = wib >> 3;
    const int u = bid * 8 + slot;
    const size_t co = (size_t)half * 512;

    float4 wr[16];                     // register-resident rW_hh half-rows (live from P8)
    float4 wb[12];                     // pipelined goal-layer weight buffer (head only)
    float creg = 0.f, rxi = 0.f, rxf = 0.f, rxg = 0.f, rxo = 0.f;
    float rbase = 0.f, rgoal = 0.f;

    // load next goal layer's 3 row-fragments into wb (plain LDG, full MLP)
    auto loadwb = [&](const float* W, int rsf) {
        const float4* p0 = (const float4*)(W + (size_t)u * rsf + co);
        const float4* p1 = (const float4*)(W + (size_t)(u + 2048) * rsf + co);
        const float4* p2 = (const float4*)(W + (size_t)(u + 3072) * rsf + co);
#pragma unroll
        for (int i = 0; i < 4; ++i) {
            int idx = lane + (i << 5);
            wb[i]     = __ldg(p0 + idx);
            wb[4 + i] = __ldg(p1 + idx);
            wb[8 + i] = __ldg(p2 + idx);
        }
    };

    // ---------- P0: maxpool + rb + stream multi-reuse weights (Wp, rW_ih) ----------
    {
        const int r0 = bid * 32;
        float m0 = -FLT_MAX, m1 = -FLT_MAX;
        for (int r = r0; r < r0 + 32; ++r) {
            m0 = fmaxf(m0, __ldcg(&tsn[(size_t)r * HD + tid]));
            m1 = fmaxf(m1, __ldcg(&tsn[(size_t)r * HD + 512 + tid]));
        }
        atomicMax(&s_maxu[tid], encf(m0));
        atomicMax(&s_maxu[tid + 512], encf(m1));
        for (int i = gtid; i < 4096; i += NBC * NT) s_rb[i] = rb_ih[i] + rb_hh[i];

        float acc = 0.f;
        const size_t nst = (size_t)NBC * NT;
        auto stream_lin = [&](const float* b, size_t nfl) {
            const float4* p4 = (const float4*)b;
            const size_t n4 = nfl >> 2;
            for (size_t i = gtid; i < n4; i += nst * 4) {
#pragma unroll
                for (int k = 0; k < 4; ++k) {
                    size_t idx = i + (size_t)k * nst;
                    if (idx < n4) {
                        float4 v = __ldcg(p4 + idx);
                        acc += v.x + v.y + v.z + v.w;
                    }
                }
            }
        };
        stream_lin(Wp, (size_t)1024 * 3072);          // 12 MB (22 reuses)
        stream_lin(rW_ih, (size_t)4096 * 2048);       // 32 MB (2 reuses)
        asm volatile("" :: "f"(acc));
    }
    gridbar(base, 1);

    // ---------- P2: fs = W_fe @ maxv + b_fe; issue L0 weight loads ----------
    {
        if (tid < 256) {
            uint4 k = ((const uint4*)s_maxu)[tid];
            float4 f;
            f.x = __uint_as_float((k.x & 0x80000000u) ? (k.x & 0x7FFFFFFFu) : ~k.x);
            f.y = __uint_as_float((k.y & 0x80000000u) ? (k.y & 0x7FFFFFFFu) : ~k.y);
            f.z = __uint_as_float((k.z & 0x80000000u) ? (k.z & 0x7FFFFFFFu) : ~k.z);
            f.w = __uint_as_float((k.w & 0x80000000u) ? (k.w & 0x7FFFFFFFu) : ~k.w);
            ((float4*)sh_x)[tid] = f;
        }
        __syncthreads();
        const float4* xs4 = (const float4*)(sh_x + co);
        const float4* w0 = (const float4*)(W_fe + (size_t)u * HD + co);
        float a0 = 0.f, a1 = 0.f;
#pragma unroll
        for (int i = 0; i < 2; ++i) {
            int idx = lane + (i << 6);
            float4 x0 = xs4[idx], v0 = w0[idx];
            float4 x1 = xs4[idx + 32], v1 = w0[idx + 32];
            FMA4(a0, v0, x0); FMA4(a1, v1, x1);
        }
        loadwb(gW_ih0, 2048);          // layer-0 weights in flight across the barrier
        float p = warp_red(a0 + a1);
        if (lane == 0) sh_part[wib][0] = p;
        __syncthreads();
        if (wib == 0 && lane < 8) {
            int uu = bid * 8 + lane;
            s_fs[uu] = sh_part[lane][0] + sh_part[lane + 8][0] + b_fe[uu];
        }
    }
    gridbar(base, 2);

    // ---------- P3..P7: goal layers 0..4 from register-pipelined weights ----------
    if (gtid < HD) s_maxu[gtid] = 0;   // reset for next call
    for (int l = 0; l <= 4; ++l) {
        const float* xin = (l == 0) ? s_fs : s_gh[l - 1];
        const float* bi = gb_ih + (size_t)l * 4096;
        const float* bh = gb_hh + (size_t)l * 4096;
        if (tid < 256) ((float4*)sh_x)[tid] = ((const float4*)xin)[tid];
        __syncthreads();
        const float4* xs4 = (const float4*)(sh_x + co);
        float a0 = 0.f, a1 = 0.f, a2 = 0.f;
#pragma unroll
        for (int i = 0; i < 4; ++i) {
            int idx = lane + (i << 5);
            float4 xq = xs4[idx];
            FMA4(a0, wb[i], xq);
            FMA4(a1, wb[4 + i], xq);
            FMA4(a2, wb[8 + i], xq);
        }
        if (l < 4) loadwb(gW_ihR + (size_t)l * 4096 * 1024, 1024);  // next layer in flight
#pragma unroll
        for (int o = 16; o; o >>= 1) {
            a0 += __shfl_xor_sync(0xffffffffu, a0, o);
            a1 += __shfl_xor_sync(0xffffffffu, a1, o);
            a2 += __shfl_xor_sync(0xffffffffu, a2, o);
        }
        if (lane == 0) { sh_part[wib][0] = a0; sh_part[wib][1] = a1; sh_part[wib][2] = a2; }
        __syncthreads();
        if (wib == 0 && lane < 8) {
            int uu = bid * 8 + lane;
            float gi = sh_part[lane][0] + sh_part[lane + 8][0] + bi[uu] + bh[uu];
            float gg = sh_part[lane][1] + sh_part[lane + 8][1] + bi[uu + 2048] + bh[uu + 2048];
            float go = sh_part[lane][2] + sh_part[lane + 8][2] + bi[uu + 3072] + bh[uu + 3072];
            float cn = sigf(gi) * tanhfast(gg);
            s_gh[l][uu] = sigf(go) * tanhfast(cn);
        }
        gridbar(base, 3 + l);
    }
    const float* goal = s_gh[4];

    // ---------- P8: wr load first (overlaps); E1 xpart(+h0,c0) to REGISTERS; Wp base ----------
    {
        // rW_hh half-rows -> registers, issued early so DRAM latency overlaps the dots
        {
            const float4* wbp = (const float4*)(rW_hh + (size_t)u * HD + co);
            const int T4 = 262144;   // 1024*1024/4
#pragma unroll
            for (int i = 0; i < 4; ++i) {
                int idx = lane + (i << 5);
                wr[4 * i + 0] = __ldg(wbp + idx);
                wr[4 * i + 1] = __ldg(wbp + idx + T4);
                wr[4 * i + 2] = __ldg(wbp + idx + 2 * T4);
                wr[4 * i + 3] = __ldg(wbp + idx + 3 * T4);
            }
        }
        if (tid < 256) ((float4*)sh_x)[tid] = ((const float4*)s_fs)[tid];
        else           ((float4*)sh_x)[tid] = ((const float4*)goal)[tid - 256];
        __syncthreads();
        const float4* xF4 = (const float4*)(sh_x + co);
        const float4* xG4 = (const float4*)(sh_x + 1024 + co);
        const float4* w0 = (const float4*)(rW_ih + (size_t)u * 2048 + 1024 + co);
        const float4* w4 = (const float4*)(Wp + (size_t)u * 3072 + co);
        const float4* w5 = (const float4*)(Wp + (size_t)u * 3072 + 2048 + co);
        const int S4 = 524288;   // 1024 rows * 2048 floats / 4
        float a0 = 0.f, a1 = 0.f, a2 = 0.f, a3 = 0.f, a4 = 0.f, a5 = 0.f;
#pragma unroll
        for (int i = 0; i < 4; ++i) {
            int idx = lane + (i << 5);
            float4 xF = xF4[idx];
            float4 xG = xG4[idx];
            float4 v0 = w0[idx];
            float4 v1 = w0[idx + S4];
            float4 v2 = w0[idx + 2 * S4];
            float4 v3 = w0[idx + 3 * S4];
            float4 v4 = w4[idx];
            float4 v5 = w5[idx];
            FMA4(a0, v0, xF); FMA4(a1, v1, xF); FMA4(a2, v2, xF);
            FMA4(a3, v3, xF); FMA4(a4, v4, xF); FMA4(a5, v5, xG);
        }
#pragma unroll
        for (int o = 16; o; o >>= 1) {
            a0 += __shfl_xor_sync(0xffffffffu, a0, o);
            a1 += __shfl_xor_sync(0xffffffffu, a1, o);
            a2 += __shfl_xor_sync(0xffffffffu, a2, o);
            a3 += __shfl_xor_sync(0xffffffffu, a3, o);
            a4 += __shfl_xor_sync(0xffffffffu, a4, o);
            a5 += __shfl_xor_sync(0xffffffffu, a5, o);
        }
        if (lane == 0) {
            sh_part[wib][0] = a0; sh_part[wib][1] = a1; sh_part[wib][2] = a2;
            sh_part[wib][3] = a3; sh_part[wib][4] = a4; sh_part[wib][5] = a5;
        }
        __syncthreads();
        if (wib == 0 && lane < 8) {
            int uu = bid * 8 + lane;
            rxi = sh_part[lane][0] + sh_part[lane + 8][0] + s_rb[uu];
            rxf = sh_part[lane][1] + sh_part[lane + 8][1] + s_rb[uu + 1024];
            rxg = sh_part[lane][2] + sh_part[lane + 8][2] + s_rb[uu + 2048];
            rxo = sh_part[lane][3] + sh_part[lane + 8][3] + s_rb[uu + 3072];
            rbase = sh_part[lane][4] + sh_part[lane + 8][4]
                  + sh_part[lane][5] + sh_part[lane + 8][5] + bp[uu];
            rgoal = goal[uu];
            float cn = sigf(rxi) * tanhfast(rxg);
            creg = cn;
            s_a[0][0][uu] = sigf(rxo) * tanhfast(cn);
        }
    }
    gridbar(base, 8);

    // ---------- Expansion 1 (j=1..10, barriers 9..18) ----------
    for (int j = 1; j <= 10; ++j)
        expand_phase_reg(0, j, wr, Wp,
                         creg, rxi, rxf, rxg, rxo, rbase, rgoal,
                         bid, wib, lane, sh_part, base, 8 + j);

    // ---------- E2_pre (merged, block-local): dv0+bd0, istar, gates+base+h0 ----------
    {
        if (wib < 10) {
            const float* p = s_dpart[0][wib];
            float acc = p[lane] + p[lane + 32] + p[lane + 64] + p[lane + 96];
            acc = warp_red(acc);
            if (lane == 0) sh_dv0[wib] = acc * (1.0f / 1024.0f);
        } else if (wib == 10) {
            float acc = 0.0f;
            for (int i = lane; i < HD; i += 32) {
                float df = s_fs[i] - goal[i];
                acc = fmaf(df, df, acc);
            }
            acc = warp_red(acc);
            if (lane == 0) sh_bd0 = acc * (1.0f / 1024.0f);
        }
        __syncthreads();
        if (tid == 0) {
            float bd = sh_bd0, best = FLT_MAX; int istar = 0;
#pragma unroll
            for (int jj = 0; jj < 10; ++jj) {
                float dj = sh_dv0[jj];
                float s = bd - dj;
                if (s < best) { best = s; istar = jj; }
                if (dj < bd) bd = dj;
            }
            sh_istar = istar;
        }
        __syncthreads();
        const int istar = sh_istar;
        const float* a2in = s_a[0][istar];
        const float* f2in = s_f[0][istar];
        for (int t = tid; t < 768; t += NT) {
            int which = t >> 8, idx = t & 255;
            const float* src = (which == 0) ? a2in : (which == 1) ? f2in : goal;
            ((float4*)sh_x)[t] = ((const float4*)src)[idx];
        }
        __syncthreads();
        // block-local: this block's 8 rows' E2 gates (2048-wide) + Wp base
        const float4* xA4 = (const float4*)(sh_x + co);
        const float4* xF4 = (const float4*)(sh_x + 1024 + co);
        const float4* xG4 = (const float4*)(sh_x + 2048 + co);
        const float4* r0 = (const float4*)(rW_ih + (size_t)u * 2048 + co);
        const float4* r1 = (const float4*)(rW_ih + (size_t)u * 2048 + 1024 + co);
        const float4* w4 = (const float4*)(Wp + (size_t)u * 3072 + co);
        const float4* w5 = (const float4*)(Wp + (size_t)u * 3072 + 2048 + co);
        const int GS4 = 524288;   // 1024 rows * 2048 floats / 4
        float g0 = 0.f, g1 = 0.f, g2 = 0.f, g3 = 0.f, bb = 0.f;
#pragma unroll
        for (int i = 0; i < 4; ++i) {
            int idx = lane + (i << 5);
            float4 xa = xA4[idx];
            float4 xf = xF4[idx];
            float4 xg = xG4[idx];
            float4 va0 = r0[idx];            float4 vf0 = r1[idx];
            float4 va1 = r0[idx + GS4];      float4 vf1 = r1[idx + GS4];
            float4 va2 = r0[idx + 2 * GS4];  float4 vf2 = r1[idx + 2 * GS4];
            float4 va3 = r0[idx + 3 * GS4];  float4 vf3 = r1[idx + 3 * GS4];
            float4 v4 = w4[idx];
            float4 v5 = w5[idx];
            FMA4(g0, va0, xa); FMA4(g0, vf0, xf);
            FMA4(g1, va1, xa); FMA4(g1, vf1, xf);
            FMA4(g2, va2, xa); FMA4(g2, vf2, xf);
            FMA4(g3, va3, xa); FMA4(g3, vf3, xf);
            FMA4(bb, v4, xf);  FMA4(bb, v5, xg);
        }
#pragma unroll
        for (int o = 16; o; o >>= 1) {
            g0 += __shfl_xor_sync(0xffffffffu, g0, o);
            g1 += __shfl_xor_sync(0xffffffffu, g1, o);
            g2 += __shfl_xor_sync(0xffffffffu, g2, o);
            g3 += __shfl_xor_sync(0xffffffffu, g3, o);
            bb += __shfl_xor_sync(0xffffffffu, bb, o);
        }
        if (lane == 0) {
            sh_part[wib][0] = g0; sh_part[wib][1] = g1; sh_part[wib][2] = g2;
            sh_part[wib][3] = g3; sh_part[wib][4] = bb;
        }
        // block 0 emits f2in while its warps are at it
        if (bid == 0) {
            for (int t = tid; t < HD; t += NT) out[OFF_F2 + t] = sh_x[1024 + t];
        }
        __syncthreads();
        if (wib == 0 && lane < 8) {
            int uu = bid * 8 + lane;
            rxi = sh_part[lane][0] + sh_part[lane + 8][0] + s_rb[uu];
            rxf = sh_part[lane][1] + sh_part[lane + 8][1] + s_rb[uu + 1024];
            rxg = sh_part[lane][2] + sh_part[lane + 8][2] + s_rb[uu + 2048];
            rxo = sh_part[lane][3] + sh_part[lane + 8][3] + s_rb[uu + 3072];
            rbase = sh_part[lane][4] + sh_part[lane + 8][4] + bp[uu];
            float cn = sigf(rxi) * tanhfast(rxg);
            creg = cn;
            s_a[1][0][uu] = sigf(rxo) * tanhfast(cn);
        }
    }
    gridbar(base, 19);

    // ---------- Expansion 2 (j=1..10, barriers 20..29) ----------
    for (int j = 1; j <= 10; ++j)
        expand_phase_reg(1, j, wr, Wp,
                         creg, rxi, rxf, rxg, rxo, rbase, rgoal,
                         bid, wib, lane, sh_part, base, 19 + j);

    // ---------- Final: d[1][*] reduce, scan + outputs (no more barriers) ----------
    {
        if (wib < 10) {
            const float* p = s_dpart[1][wib];
            float acc = p[lane] + p[lane + 32] + p[lane + 64] + p[lane + 96];
            acc = warp_red(acc);
            if (lane == 0) sh_dv1[wib] = acc * (1.0f / 1024.0f);
        }
        __syncthreads();
        if (tid == 0) {
            float bd = sh_bd0, best = FLT_MAX; int istar = 0;
            float s1[10], s2[10];
#pragma unroll
            for (int jj = 0; jj < 10; ++jj) {
                float dj = sh_dv0[jj];
                s1[jj] = bd - dj;
                if (s1[jj] < best) { best = s1[jj]; istar = jj; }
                if (dj < bd) bd = dj;
            }
#pragma unroll
            for (int jj = 0; jj < 10; ++jj) {
                float dj = sh_dv1[jj];
                s2[jj] = bd - dj;
                if (dj < bd) bd = dj;
            }
            float b0 = FLT_MAX, b1 = FLT_MAX; int i0 = 0, i1 = 0;
#pragma unroll
            for (int k = 0; k < 20; ++k) {
                float v = (k < 10) ? ((k == istar) ? FLT_MAX : s1[k]) : s2[k - 10];
                if (v < b0) { b1 = b0; i1 = i0; b0 = v; i0 = k; }
                else if (v < b1) { b1 = v; i1 = k; }
            }
            sh_istar = istar; sh_i0 = i0; sh_i1 = i1;
        }
        __syncthreads();
        const int istar = sh_istar;
        const float* a2in = s_a[0][istar];
        const float* f2in = s_f[0][istar];

        for (int t = tid; t < 2048; t += NT) {
            int which = t >> 10, col = t & 1023;
            int idx = which ? sh_i1 : sh_i0;
            float pa;
            if (idx < 10) pa = s_a[0][idx][col] * 0.5f;
            else          pa = (a2in[col] + s_a[1][idx - 10][col]) * (1.0f / 3.0f);
            sh_pa[which][col] = pa;
        }
        if (bid == 0) {
            for (int t = tid; t < 2048; t += NT) {
                int which = t >> 10, col = t & 1023;
                int idx = which ? sh_i1 : sh_i0;
                float pfv;
                if (idx < 10) pfv = (s_fs[col] + s_f[0][idx][col]) * 0.5f;
                else          pfv = (s_fs[col] + f2in[col] + s_f[1][idx - 10][col]) * (1.0f / 3.0f);
                out[OFF_PF + which * HD + col] = pfv;
                out[OFF_PG + which * HD + col] = goal[col];
            }
        }
        __syncthreads();

        // paired prediction dots across compute warps
        for (int rr = gwid; rr < 2990; rr += NWARPC) {
            const float* W; const float* bias; int off, rows, r;
            if (rr < 2513)      { W = We2a; bias = be2a; off = OFF_PA; rows = 2513; r = rr; }
            else if (rr < 2638) { W = We2v; bias = be2v; off = OFF_PV; rows = 125;  r = rr - 2513; }
            else                { W = We2n; bias = be2n; off = OFF_PN; rows = 352;  r = rr - 2638; }
            const float4* row4 = (const float4*)(W + (size_t)r * HD);
            float a0 = 0.f, a1 = 0.f;
#pragma unroll
            for (int i = 0; i < 8; ++i) {
                int idx = lane + (i << 5);
                float4 wv = row4[idx];
                float4 ua = ((const float4*)sh_pa[0])[idx];
                float4 ub = ((const float4*)sh_pa[1])[idx];
                FMA4(a0, wv, ua);
                FMA4(a1, wv, ub);
            }
#pragma unroll
            for (int o = 16; o; o >>= 1) {
                a0 += __shfl_xor_sync(0xffffffffu, a0, o);
                a1 += __shfl_xor_sync(0xffffffffu, a1, o);
            }
            if (lane == 0) {
                out[off + r] = a0 + bias[r];
                out[off + rows + r] = a1 + bias[r];
            }
        }
    }
}

extern "C" void kernel_launch(void* const* d_in, const int* in_sizes, int n_in,
                              void* d_out, int out_size) {
    const float* tsn    = (const float*)d_in[0];
    const float* W_fe   = (const float*)d_in[1];
    const float* b_fe   = (const float*)d_in[2];
    const float* gW_ih0 = (const float*)d_in[3];
    const float* gW_ihR = (const float*)d_in[4];
    // d_in[5] = gW_hh : multiplied by zero hidden state everywhere -> unused
    const float* gb_ih  = (const float*)d_in[6];
    const float* gb_hh  = (const float*)d_in[7];
    const float* rW_ih  = (const float*)d_in[8];
    const float* rW_hh  = (const float*)d_in[9];
    const float* rb_ih  = (const float*)d_in[10];
    const float* rb_hh  = (const float*)d_in[11];
    const float* Wp     = (const float*)d_in[12];
    const float* bp     = (const float*)d_in[13];
    const float* We2a   = (const float*)d_in[14];
    const float* be2a   = (const float*)d_in[15];
    const float* We2v   = (const float*)d_in[16];
    const float* be2v   = (const float*)d_in[17];
    const float* We2n   = (const float*)d_in[18];
    const float* be2n   = (const float*)d_in[19];

    va_kernel<<<NB, NT>>>(tsn, W_fe, b_fe, gW_ih0, gW_ihR, gb_ih, gb_hh,
                          rW_ih, rW_hh, rb_ih, rb_hh, Wp, bp,
                          We2a, be2a, We2v, be2v, We2n, be2n,
                          (float*)d_out);
}